// round 12
// baseline (speedup 1.0000x reference)
#include <cuda_runtime.h>

#define BB 2
#define NN 262144
#define SS 24
#define TOT (BB*NN)
#define EPSV 1e-4f
#define NPART 64

// ---- scratch (no allocation allowed; __device__ globals) ----
__device__ float  g_wm[TOT];
__device__ float  g_u[TOT];
__device__ float  g_v[TOT];
__device__ double g_partA[NPART];   // |A| partials
__device__ double g_partV[NPART];   // valid partials
__device__ double g_partD[NPART];   // diff^2 partials

// ---------------------------------------------------------------------------
__device__ __forceinline__ float warpReduceSum(float v) {
    #pragma unroll
    for (int o = 16; o > 0; o >>= 1) v += __shfl_down_sync(0xffffffffu, v, o);
    return v;
}

__device__ __forceinline__ void load_nbr24(const int* __restrict__ nbr,
                                           long long i, int* nn) {
    const int4* nb4 = (const int4*)(nbr + i * SS);
    #pragma unroll
    for (int k = 0; k < 6; k++) {
        int4 q = nb4[k];
        nn[4*k+0] = q.x; nn[4*k+1] = q.y; nn[4*k+2] = q.z; nn[4*k+3] = q.w;
    }
}

// Warp-private stage of 32 nodes x 25 G-coeffs (800 floats, linear copy).
__device__ __forceinline__ void warp_stage_g25(const float* __restrict__ G,
                                               int warpNode0, float* shw, int lane) {
    const float* gBase = G + (long long)warpNode0 * 25;
    #pragma unroll
    for (int k = 0; k < 25; k++)
        shw[k * 32 + lane] = gBase[k * 32 + lane];
    __syncwarp();
}

// Warp-private stage of 32 nodes x 24 Ao-coeffs, padded row 24->25.
__device__ __forceinline__ void warp_stage_a24(const float* __restrict__ Ao,
                                               int warpNode0, float* shw, int lane) {
    const float* aBase = Ao + (long long)warpNode0 * SS;
    #pragma unroll
    for (int k = 0; k < 24; k++) {
        int e = k * 32 + lane;          // e = m*24 + c
        shw[e + e / 24] = aBase[e];     // -> m*25 + c
    }
    __syncwarp();
}

// ---------------------------------------------------------------------------
// zero g_u and partial arrays (keeps g_u L2-resident for scatter)
__global__ __launch_bounds__(256) void k_zero() {
    long long i = (long long)blockIdx.x * blockDim.x + threadIdx.x;
    if (i < NPART) { g_partA[i] = 0.0; g_partV[i] = 0.0; g_partD[i] = 0.0; }
    float4* u4 = (float4*)g_u;
    if (i < TOT / 4) u4[i] = make_float4(0.f, 0.f, 0.f, 0.f);
}

// K1: wm = w*vm ; u += diag + G^T scatter (25 atomics/node). No barriers.
__global__ __launch_bounds__(256) void k_scatter(const float* __restrict__ G,
                                                 const float* __restrict__ w,
                                                 const float* __restrict__ vm,
                                                 const int* __restrict__ nbr) {
    __shared__ float sh[8 * 800];
    int tid  = threadIdx.x;
    int lane = tid & 31;
    int wid  = tid >> 5;
    int node0 = blockIdx.x * 256;
    long long i = node0 + tid;
    int base = (i >= NN) ? NN : 0;
    float* shw = sh + wid * 800;

    warp_stage_g25(G, node0 + wid * 32, shw, lane);
    const float* my = shw + lane * 25;

    float wmv = w[i] * vm[i];
    g_wm[i] = wmv;

    int nn[24];
    load_nbr24(nbr, i, nn);

    atomicAdd(&g_u[i], wmv * my[0]);                  // diagonal (coalesced)
    #pragma unroll
    for (int j = 0; j < SS; j++) {
        int nb = nn[j];
        if ((unsigned)nb < (unsigned)NN)
            atomicAdd(&g_u[base + nb], wmv * my[1 + j]);
    }
}

// K2: v = G u + eps*wm (+ |A| and valid warp-partials). Barrier-free.
__global__ __launch_bounds__(256) void k_gather_v(const float* __restrict__ G,
                                                  const float* __restrict__ Ad,
                                                  const float* __restrict__ Ao,
                                                  const float* __restrict__ vm,
                                                  const int* __restrict__ nbr) {
    __shared__ float sh[8 * 800];
    int tid  = threadIdx.x;
    int lane = tid & 31;
    int wid  = tid >> 5;
    int node0 = blockIdx.x * 256;
    long long i = node0 + tid;
    int base = (i >= NN) ? NN : 0;
    float* shw = sh + wid * 800;

    warp_stage_g25(G, node0 + wid * 32, shw, lane);
    const float* my = shw + lane * 25;

    int nn[24];
    load_nbr24(nbr, i, nn);
    float xs[24];
    #pragma unroll
    for (int j = 0; j < SS; j++)
        xs[j] = ((unsigned)nn[j] < (unsigned)NN) ? g_u[base + nn[j]] : 0.f;

    float acc = g_u[i] * my[0];
    #pragma unroll
    for (int j = 0; j < SS; j++)
        acc = fmaf(xs[j], my[1 + j], acc);

    g_v[i] = acc + EPSV * g_wm[i];

    // flat |A| partial (association-free bijection over Ao, coalesced float4)
    float v = vm[i];
    float s = fabsf(Ad[i]);
    const float4* A4 = (const float4*)Ao;             // TOT*6 float4 total
    #pragma unroll
    for (int k = 0; k < 6; k++) {
        float4 a = A4[(long long)k * TOT + i];
        s += fabsf(a.x) + fabsf(a.y) + fabsf(a.z) + fabsf(a.w);
    }
    float ws = warpReduceSum(s);
    float wv = warpReduceSum(v);
    if (lane == 0) {
        int slot = (blockIdx.x * 8 + wid) & (NPART - 1);
        atomicAdd(&g_partA[slot], (double)ws);
        atomicAdd(&g_partV[slot], (double)wv);
    }
}

// K3: y = A v ; z = y*s_inv ; diff^2 warp-partials. Barrier-free.
// Each warp derives s_inv itself from the 64 L2-resident partials (no k_norm).
__global__ __launch_bounds__(256) void k_gather_y(const float* __restrict__ Ad,
                                                  const float* __restrict__ Ao,
                                                  const float* __restrict__ vm,
                                                  const int* __restrict__ nbr) {
    __shared__ float sh[8 * 800];
    int tid  = threadIdx.x;
    int lane = tid & 31;
    int wid  = tid >> 5;
    int node0 = blockIdx.x * 256;
    long long i = node0 + tid;
    int base = (i >= NN) ? NN : 0;
    float* shw = sh + wid * 800;

    warp_stage_a24(Ao, node0 + wid * 32, shw, lane);
    const float* my = shw + lane * 25;

    // per-warp norm reduction: 2 cached double loads/lane + shfl tree
    double a  = g_partA[lane] + g_partA[lane + 32];
    double vv = g_partV[lane] + g_partV[lane + 32];
    #pragma unroll
    for (int o = 16; o > 0; o >>= 1) {
        a  += __shfl_down_sync(0xffffffffu, a,  o);
        vv += __shfl_down_sync(0xffffffffu, vv, o);
    }
    float s_inv = 0.f;
    if (lane == 0) {
        double norm = a / (vv * 25.0 + 1e-6);
        s_inv = (float)(1.0 / (norm + 1e-8));
    }
    s_inv = __shfl_sync(0xffffffffu, s_inv, 0);

    int nn[24];
    load_nbr24(nbr, i, nn);
    float xs[24];
    #pragma unroll
    for (int j = 0; j < SS; j++)
        xs[j] = ((unsigned)nn[j] < (unsigned)NN) ? g_v[base + nn[j]] : 0.f;

    float acc = g_v[i] * Ad[i];
    #pragma unroll
    for (int j = 0; j < SS; j++)
        acc = fmaf(xs[j], my[j], acc);

    float z = acc * s_inv;
    float d = (z - g_wm[i]) * vm[i];
    float wd = warpReduceSum(d * d);
    if (lane == 0) {
        int slot = (blockIdx.x * 8 + wid) & (NPART - 1);
        atomicAdd(&g_partD[slot], (double)wd);
    }
}

__global__ void k_final(float* out) {
    int t = threadIdx.x;                // 64 threads
    double d = g_partD[t];
    double v = g_partV[t];
    #pragma unroll
    for (int o = 16; o > 0; o >>= 1) {
        d += __shfl_down_sync(0xffffffffu, d, o);
        v += __shfl_down_sync(0xffffffffu, v, o);
    }
    __shared__ double shD[2], shV[2];
    if ((t & 31) == 0) { shD[t >> 5] = d; shV[t >> 5] = v; }
    __syncthreads();
    if (t == 0)
        out[0] = (float)((shD[0] + shD[1]) / (shV[0] + shV[1] + 1e-6));
}

// ---------------------------------------------------------------------------
extern "C" void kernel_launch(void* const* d_in, const int* in_sizes, int n_in,
                              void* d_out, int out_size) {
    const float* G   = (const float*)d_in[0];   // [2,N,25]
    const float* Ad  = (const float*)d_in[1];   // [2,N,1]
    const float* Ao  = (const float*)d_in[2];   // [2,N,24]
    const float* w   = (const float*)d_in[3];   // [2,N,1]
    const float* vm  = (const float*)d_in[4];   // [2,N,1]
    const int*   nbr = (const int*)d_in[5];     // [2,N,24] int32
    float* out = (float*)d_out;

    const int T = 256;
    const int nodeBlocks = TOT / T;             // 2048, exact
    const int zeroBlocks = TOT / 4 / T;         // 512

    k_zero    <<<zeroBlocks, T>>>();
    k_scatter <<<nodeBlocks, T>>>(G, w, vm, nbr);
    k_gather_v<<<nodeBlocks, T>>>(G, Ad, Ao, vm, nbr);
    k_gather_y<<<nodeBlocks, T>>>(Ad, Ao, vm, nbr);
    k_final   <<<1, 64>>>(out);
}

// round 13
// speedup vs baseline: 1.0502x; 1.0502x over previous
#include <cuda_runtime.h>

#define BB 2
#define NN 262144
#define SS 24
#define TOT (BB*NN)
#define EPSV 1e-4f
#define NPART 64

// ---- scratch (no allocation allowed; __device__ globals) ----
__device__ float  g_wm[TOT];
__device__ float  g_u[TOT];
__device__ float  g_v[TOT];
__device__ double g_partA[NPART];   // |A| partials
__device__ double g_partV[NPART];   // valid partials
__device__ double g_partD[NPART];   // diff^2 partials
__device__ float  g_sinv;           // 1/(norm+1e-8), set by gather_v last block
__device__ unsigned g_count;        // completion counter (self-resetting)

// ---------------------------------------------------------------------------
__device__ __forceinline__ float warpReduceSum(float v) {
    #pragma unroll
    for (int o = 16; o > 0; o >>= 1) v += __shfl_down_sync(0xffffffffu, v, o);
    return v;
}

__device__ __forceinline__ void load_nbr24(const int* __restrict__ nbr,
                                           long long i, int* nn) {
    const int4* nb4 = (const int4*)(nbr + i * SS);
    #pragma unroll
    for (int k = 0; k < 6; k++) {
        int4 q = nb4[k];
        nn[4*k+0] = q.x; nn[4*k+1] = q.y; nn[4*k+2] = q.z; nn[4*k+3] = q.w;
    }
}

// Warp-private stage of 32 nodes x 25 G-coeffs (800 floats, linear copy).
__device__ __forceinline__ void warp_stage_g25(const float* __restrict__ G,
                                               int warpNode0, float* shw, int lane) {
    const float* gBase = G + (long long)warpNode0 * 25;
    #pragma unroll
    for (int k = 0; k < 25; k++)
        shw[k * 32 + lane] = gBase[k * 32 + lane];
    __syncwarp();
}

// Warp-private stage of 32 nodes x 24 Ao-coeffs, padded row 24->25.
__device__ __forceinline__ void warp_stage_a24(const float* __restrict__ Ao,
                                               int warpNode0, float* shw, int lane) {
    const float* aBase = Ao + (long long)warpNode0 * SS;
    #pragma unroll
    for (int k = 0; k < 24; k++) {
        int e = k * 32 + lane;          // e = m*24 + c
        shw[e + e / 24] = aBase[e];     // -> m*25 + c
    }
    __syncwarp();
}

// ---------------------------------------------------------------------------
// zero g_u and partial arrays (keeps g_u L2-resident for scatter)
__global__ __launch_bounds__(256) void k_zero() {
    long long i = (long long)blockIdx.x * blockDim.x + threadIdx.x;
    if (i < NPART) { g_partA[i] = 0.0; g_partV[i] = 0.0; g_partD[i] = 0.0; }
    float4* u4 = (float4*)g_u;
    if (i < TOT / 4) u4[i] = make_float4(0.f, 0.f, 0.f, 0.f);
}

// K1: wm = w*vm ; u += diag + G^T scatter (25 atomics/node). No barriers.
__global__ __launch_bounds__(256) void k_scatter(const float* __restrict__ G,
                                                 const float* __restrict__ w,
                                                 const float* __restrict__ vm,
                                                 const int* __restrict__ nbr) {
    __shared__ float sh[8 * 800];
    int tid  = threadIdx.x;
    int lane = tid & 31;
    int wid  = tid >> 5;
    int node0 = blockIdx.x * 256;
    long long i = node0 + tid;
    int base = (i >= NN) ? NN : 0;
    float* shw = sh + wid * 800;

    warp_stage_g25(G, node0 + wid * 32, shw, lane);
    const float* my = shw + lane * 25;

    float wmv = w[i] * vm[i];
    g_wm[i] = wmv;

    int nn[24];
    load_nbr24(nbr, i, nn);

    atomicAdd(&g_u[i], wmv * my[0]);                  // diagonal (coalesced)
    #pragma unroll
    for (int j = 0; j < SS; j++) {
        int nb = nn[j];
        if ((unsigned)nb < (unsigned)NN)
            atomicAdd(&g_u[base + nb], wmv * my[1 + j]);
    }
}

// K2: v = G u + eps*wm (+ |A|/valid partials; last block computes g_sinv).
__global__ __launch_bounds__(256) void k_gather_v(const float* __restrict__ G,
                                                  const float* __restrict__ Ad,
                                                  const float* __restrict__ Ao,
                                                  const float* __restrict__ vm,
                                                  const int* __restrict__ nbr) {
    __shared__ float sh[8 * 800];
    int tid  = threadIdx.x;
    int lane = tid & 31;
    int wid  = tid >> 5;
    int node0 = blockIdx.x * 256;
    long long i = node0 + tid;
    int base = (i >= NN) ? NN : 0;
    float* shw = sh + wid * 800;

    warp_stage_g25(G, node0 + wid * 32, shw, lane);
    const float* my = shw + lane * 25;

    int nn[24];
    load_nbr24(nbr, i, nn);
    float xs[24];
    #pragma unroll
    for (int j = 0; j < SS; j++)
        xs[j] = ((unsigned)nn[j] < (unsigned)NN) ? g_u[base + nn[j]] : 0.f;

    float acc = g_u[i] * my[0];
    #pragma unroll
    for (int j = 0; j < SS; j++)
        acc = fmaf(xs[j], my[1 + j], acc);

    g_v[i] = acc + EPSV * g_wm[i];

    // flat |A| partial (association-free bijection over Ao, coalesced float4)
    float v = vm[i];
    float s = fabsf(Ad[i]);
    const float4* A4 = (const float4*)Ao;             // TOT*6 float4 total
    #pragma unroll
    for (int k = 0; k < 6; k++) {
        float4 a = A4[(long long)k * TOT + i];
        s += fabsf(a.x) + fabsf(a.y) + fabsf(a.z) + fabsf(a.w);
    }
    float ws = warpReduceSum(s);
    float wv = warpReduceSum(v);
    if (lane == 0) {
        int slot = (blockIdx.x * 8 + wid) & (NPART - 1);
        atomicAdd(&g_partA[slot], (double)ws);
        atomicAdd(&g_partV[slot], (double)wv);
    }

    // last-block finalize: one warp reduces the 64 partials -> g_sinv
    __syncwarp();
    if (wid == 0) {
        unsigned ticket = 0;
        if (lane == 0) {
            __threadfence();
            ticket = atomicAdd(&g_count, 1u);
        }
        ticket = __shfl_sync(0xffffffffu, ticket, 0);
        if (ticket == gridDim.x - 1) {
            double a  = *((volatile double*)&g_partA[lane])
                      + *((volatile double*)&g_partA[lane + 32]);
            double vv = *((volatile double*)&g_partV[lane])
                      + *((volatile double*)&g_partV[lane + 32]);
            #pragma unroll
            for (int o = 16; o > 0; o >>= 1) {
                a  += __shfl_down_sync(0xffffffffu, a,  o);
                vv += __shfl_down_sync(0xffffffffu, vv, o);
            }
            if (lane == 0) {
                double norm = a / (vv * 25.0 + 1e-6);
                g_sinv = (float)(1.0 / (norm + 1e-8));
                g_count = 0u;           // reset for next replay
                __threadfence();
            }
        }
    }
}

// K3: y = A v ; z = y*g_sinv ; diff^2 warp-partials. Barrier-free, uniform load.
__global__ __launch_bounds__(256) void k_gather_y(const float* __restrict__ Ad,
                                                  const float* __restrict__ Ao,
                                                  const float* __restrict__ vm,
                                                  const int* __restrict__ nbr) {
    __shared__ float sh[8 * 800];
    int tid  = threadIdx.x;
    int lane = tid & 31;
    int wid  = tid >> 5;
    int node0 = blockIdx.x * 256;
    long long i = node0 + tid;
    int base = (i >= NN) ? NN : 0;
    float* shw = sh + wid * 800;

    warp_stage_a24(Ao, node0 + wid * 32, shw, lane);
    const float* my = shw + lane * 25;

    float s_inv = g_sinv;               // uniform scalar load

    int nn[24];
    load_nbr24(nbr, i, nn);
    float xs[24];
    #pragma unroll
    for (int j = 0; j < SS; j++)
        xs[j] = ((unsigned)nn[j] < (unsigned)NN) ? g_v[base + nn[j]] : 0.f;

    float acc = g_v[i] * Ad[i];
    #pragma unroll
    for (int j = 0; j < SS; j++)
        acc = fmaf(xs[j], my[j], acc);

    float z = acc * s_inv;
    float d = (z - g_wm[i]) * vm[i];
    float wd = warpReduceSum(d * d);
    if (lane == 0) {
        int slot = (blockIdx.x * 8 + wid) & (NPART - 1);
        atomicAdd(&g_partD[slot], (double)wd);
    }
}

__global__ void k_final(float* out) {
    int t = threadIdx.x;                // 64 threads
    double d = g_partD[t];
    double v = g_partV[t];
    #pragma unroll
    for (int o = 16; o > 0; o >>= 1) {
        d += __shfl_down_sync(0xffffffffu, d, o);
        v += __shfl_down_sync(0xffffffffu, v, o);
    }
    __shared__ double shD[2], shV[2];
    if ((t & 31) == 0) { shD[t >> 5] = d; shV[t >> 5] = v; }
    __syncthreads();
    if (t == 0)
        out[0] = (float)((shD[0] + shD[1]) / (shV[0] + shV[1] + 1e-6));
}

// ---------------------------------------------------------------------------
extern "C" void kernel_launch(void* const* d_in, const int* in_sizes, int n_in,
                              void* d_out, int out_size) {
    const float* G   = (const float*)d_in[0];   // [2,N,25]
    const float* Ad  = (const float*)d_in[1];   // [2,N,1]
    const float* Ao  = (const float*)d_in[2];   // [2,N,24]
    const float* w   = (const float*)d_in[3];   // [2,N,1]
    const float* vm  = (const float*)d_in[4];   // [2,N,1]
    const int*   nbr = (const int*)d_in[5];     // [2,N,24] int32
    float* out = (float*)d_out;

    const int T = 256;
    const int nodeBlocks = TOT / T;             // 2048, exact
    const int zeroBlocks = TOT / 4 / T;         // 512

    k_zero    <<<zeroBlocks, T>>>();
    k_scatter <<<nodeBlocks, T>>>(G, w, vm, nbr);
    k_gather_v<<<nodeBlocks, T>>>(G, Ad, Ao, vm, nbr);
    k_gather_y<<<nodeBlocks, T>>>(Ad, Ao, vm, nbr);
    k_final   <<<1, 64>>>(out);
}